// round 2
// baseline (speedup 1.0000x reference)
#include <cuda_runtime.h>

#define HW 16384
#define WD 128

typedef unsigned long long u64;

// Scratch (allocation-free rule: __device__ globals)
__device__ float g_est1[2 * 128 * HW];   // 16 MB
__device__ float g_est2[2 * 128 * HW];   // 16 MB
__device__ float g_off [2 * 18  * HW];   // 2.25 MB
__device__ float g_wt  [9 * 128 * 128];  // w_def transposed to [k][c][o]

// ---- packed fp32x2 helpers (sm_103a dual-rate FP32) ------------------------
__device__ __forceinline__ u64 pk(float lo, float hi) {
    u64 r; asm("mov.b64 %0, {%1, %2};" : "=l"(r) : "f"(lo), "f"(hi)); return r;
}
__device__ __forceinline__ void upk(u64 v, float& lo, float& hi) {
    asm("mov.b64 {%0, %1}, %2;" : "=f"(lo), "=f"(hi) : "l"(v));
}
__device__ __forceinline__ u64 fma2(u64 a, u64 b, u64 c) {
    u64 d; asm("fma.rn.f32x2 %0, %1, %2, %3;" : "=l"(d) : "l"(a), "l"(b), "l"(c));
    return d;
}

// ---------------------------------------------------------------------------
// Direct 3x3 conv, stride 1, pad 1, NCHW, H=W=128, fp32x2 math.
// Block: 128 threads, output tile 16(h) x 64(w); thread: 2 rows x 4 cols,
// OC_B output channels register-blocked. 2 input channels per staging round.
// CONCAT=true: channels [0,128) from in0, [128,256) from in1.
// ---------------------------------------------------------------------------
template <int C_IN, int OC_B, bool RELU, bool CONCAT>
__global__ __launch_bounds__(128) void conv3x3_k(
    const float* __restrict__ in0, const float* __restrict__ in1,
    const float* __restrict__ wt, float* __restrict__ out,
    int C_out, int n_ocb)
{
    __shared__ __align__(16) float st[2][18 * 66];
    __shared__ u64 swd[2][OC_B * 9];

    const int tid = threadIdx.x;
    const int tx  = tid & 15;          // 16 threads across W (4 px each)
    const int ty  = tid >> 4;          // 8  threads across H (2 px each)
    const int w0  = blockIdx.x * 64;
    const int h0  = blockIdx.y * 16;
    const int b   = blockIdx.z / n_ocb;
    const int ocb = blockIdx.z % n_ocb;

    u64 acc[OC_B][2][2];
#pragma unroll
    for (int o = 0; o < OC_B; o++)
#pragma unroll
        for (int r = 0; r < 2; r++) { acc[o][r][0] = 0ull; acc[o][r][1] = 0ull; }

    for (int cc = 0; cc < C_IN; cc += 2) {
        __syncthreads();   // previous round's SMEM reads complete
#pragma unroll
        for (int s = 0; s < 2; s++) {
            const int c = cc + s;
            const float* plane;
            if (CONCAT) {
                plane = (c < 128) ? in0 + (size_t)(b * 128 + c) * HW
                                  : in1 + (size_t)(b * 128 + (c - 128)) * HW;
            } else {
                plane = in0 + (size_t)(b * C_IN + c) * HW;
            }
            for (int i = tid; i < 18 * 66; i += 128) {
                int r  = i / 66;
                int q  = i - r * 66;
                int gh = h0 - 1 + r;
                int gw = w0 - 1 + q;
                float v = 0.f;
                if ((unsigned)gh < 128u && (unsigned)gw < 128u)
                    v = __ldg(plane + gh * WD + gw);
                st[s][i] = v;
            }
        }
        // duplicated weights: swd[s][o*9+t] = (w,w)
        for (int i = tid; i < 2 * OC_B * 9; i += 128) {
            int s = i / (OC_B * 9);
            int t = i - s * (OC_B * 9);
            int o = ocb * OC_B + t / 9;
            float wv = (o < C_out)
                     ? wt[((size_t)o * C_IN + (cc + s)) * 9 + (t % 9)] : 0.f;
            swd[s][t] = pk(wv, wv);
        }
        __syncthreads();

#pragma unroll
        for (int s = 0; s < 2; s++) {
            // input pairs P[r][m] = (col m, col m+1), r = tile row ty*2+r
            u64 P[4][5];
#pragma unroll
            for (int r = 0; r < 4; r++) {
                const float* rp = st[s] + (ty * 2 + r) * 66 + tx * 4;
                float2 A = *(const float2*)rp;
                float2 Bv = *(const float2*)(rp + 2);
                float2 D = *(const float2*)(rp + 4);
                P[r][0] = pk(A.x, A.y);
                P[r][1] = pk(A.y, Bv.x);
                P[r][2] = pk(Bv.x, Bv.y);
                P[r][3] = pk(Bv.y, D.x);
                P[r][4] = pk(D.x, D.y);
            }
#pragma unroll
            for (int o = 0; o < OC_B; o++) {
#pragma unroll
                for (int ky = 0; ky < 3; ky++)
#pragma unroll
                    for (int kx = 0; kx < 3; kx++) {
                        u64 wv = swd[s][o * 9 + ky * 3 + kx];
                        acc[o][0][0] = fma2(P[ky][kx],         wv, acc[o][0][0]);
                        acc[o][0][1] = fma2(P[ky][kx + 2],     wv, acc[o][0][1]);
                        acc[o][1][0] = fma2(P[ky + 1][kx],     wv, acc[o][1][0]);
                        acc[o][1][1] = fma2(P[ky + 1][kx + 2], wv, acc[o][1][1]);
                    }
            }
        }
    }

    const int ph = h0 + ty * 2, pw = w0 + tx * 4;
#pragma unroll
    for (int o = 0; o < OC_B; o++) {
        int oc = ocb * OC_B + o;
        if (oc >= C_out) break;
        float* op = out + (size_t)(b * C_out + oc) * HW + ph * WD + pw;
#pragma unroll
        for (int r = 0; r < 2; r++) {
            float4 v;
            upk(acc[o][r][0], v.x, v.y);
            upk(acc[o][r][1], v.z, v.w);
            if (RELU) {
                v.x = fmaxf(v.x, 0.f); v.y = fmaxf(v.y, 0.f);
                v.z = fmaxf(v.z, 0.f); v.w = fmaxf(v.w, 0.f);
            }
            *(float4*)(op + r * WD) = v;
        }
    }
}

// ---------------------------------------------------------------------------
// Transpose w_def [O,C,3,3] -> g_wt [k][c][o]
// ---------------------------------------------------------------------------
__global__ void transpose_wdef(const float* __restrict__ w, float* __restrict__ wtp)
{
    int idx = blockIdx.x * 256 + threadIdx.x;
    if (idx >= 9 * 128 * 128) return;
    int o = idx & 127;
    int c = (idx >> 7) & 127;
    int k = idx >> 14;
    wtp[idx] = w[((size_t)o * 128 + c) * 9 + k];
}

// ---------------------------------------------------------------------------
// Fused deformable conv, fp32x2: block = 128 pixels (8h x 16w), ALL 128
// output channels (each pixel gathered exactly once). Per tap k: stage
// 64c x 128o weights (32 KB) twice; c-loop: 4 gathers + 64 fma2 via
// broadcast ulonglong2 SMEM reads.
// ---------------------------------------------------------------------------
__global__ __launch_bounds__(128) void deform_k(
    const float* __restrict__ ref, const float* __restrict__ off,
    const float* __restrict__ wtp, float* __restrict__ out)
{
    __shared__ __align__(16) float swt[64 * 128];  // 32 KB: [c'][o]

    const int tid = threadIdx.x;
    const int w = blockIdx.x * 16 + (tid & 15);
    const int h = blockIdx.y * 8  + (tid >> 4);
    const int b = blockIdx.z;

    u64 a2[64];
#pragma unroll
    for (int j = 0; j < 64; j++) a2[j] = 0ull;

    const float* offp = off + (size_t)b * 18 * HW + h * WD + w;
    const float* pb   = ref + (size_t)b * 128 * HW;

    for (int k = 0; k < 9; ++k) {
        // bilinear sampling parameters (per-corner validity, zero outside)
        float dy = __ldg(offp + (2 * k)     * HW);
        float dx = __ldg(offp + (2 * k + 1) * HW);
        float py = (float)(h + (k / 3) - 1) + dy;
        float px = (float)(w + (k % 3) - 1) + dx;
        float y0f = floorf(py), x0f = floorf(px);
        float wy = py - y0f, wx = px - x0f;
        int y0 = (int)y0f, x0 = (int)x0f;
        int y1 = y0 + 1,   x1 = x0 + 1;
        bool vy0 = (unsigned)y0 < 128u, vy1 = (unsigned)y1 < 128u;
        bool vx0 = (unsigned)x0 < 128u, vx1 = (unsigned)x1 < 128u;
        int y0c = min(max(y0, 0), 127), y1c = min(max(y1, 0), 127);
        int x0c = min(max(x0, 0), 127), x1c = min(max(x1, 0), 127);
        float w00 = (1.f - wy) * (1.f - wx) * ((vy0 && vx0) ? 1.f : 0.f);
        float w01 = (1.f - wy) * wx         * ((vy0 && vx1) ? 1.f : 0.f);
        float w10 = wy * (1.f - wx)         * ((vy1 && vx0) ? 1.f : 0.f);
        float w11 = wy * wx                 * ((vy1 && vx1) ? 1.f : 0.f);
        int o00 = y0c * WD + x0c, o01 = y0c * WD + x1c;
        int o10 = y1c * WD + x0c, o11 = y1c * WD + x1c;

#pragma unroll 1
        for (int half = 0; half < 2; half++) {
            __syncthreads();   // previous stage's reads complete
            const float* src = wtp + (size_t)k * 16384 + half * 64 * 128;
            for (int i = tid * 4; i < 8192; i += 512)
                *(float4*)(swt + i) = *(const float4*)(src + i);
            __syncthreads();

            const float* plc = pb + (size_t)(half * 64) * HW;
#pragma unroll 2
            for (int c = 0; c < 64; ++c) {
                const float* pl = plc + (size_t)c * HW;
                float s = w00 * __ldg(pl + o00) + w01 * __ldg(pl + o01)
                        + w10 * __ldg(pl + o10) + w11 * __ldg(pl + o11);
                u64 ss = pk(s, s);
                const ulonglong2* wr = (const ulonglong2*)(swt + c * 128);
#pragma unroll
                for (int j = 0; j < 32; j++) {
                    ulonglong2 wv = wr[j];
                    a2[2 * j]     = fma2(wv.x, ss, a2[2 * j]);
                    a2[2 * j + 1] = fma2(wv.y, ss, a2[2 * j + 1]);
                }
            }
        }
    }

    float* op = out + (size_t)b * 128 * HW + h * WD + w;
#pragma unroll
    for (int j = 0; j < 64; j++) {
        float v0, v1;
        upk(a2[j], v0, v1);
        op[(size_t)(2 * j)     * HW] = v0;
        op[(size_t)(2 * j + 1) * HW] = v1;
    }
}

// ---------------------------------------------------------------------------
extern "C" void kernel_launch(void* const* d_in, const int* in_sizes, int n_in,
                              void* d_out, int out_size)
{
    const float* x  = (const float*)d_in[0];  // input_features
    const float* rf = (const float*)d_in[1];  // reference_features
    const float* w1 = (const float*)d_in[2];  // w_est1 [128,256,3,3]
    const float* w2 = (const float*)d_in[3];  // w_est2 [128,128,3,3]
    const float* wo = (const float*)d_in[4];  // w_off  [18,128,3,3]
    const float* wd = (const float*)d_in[5];  // w_def  [128,128,3,3]
    float* out = (float*)d_out;

    const int B = in_sizes[0] / (128 * HW);   // 2

    float *e1, *e2, *of, *wtp;
    cudaGetSymbolAddress((void**)&e1,  g_est1);
    cudaGetSymbolAddress((void**)&e2,  g_est2);
    cudaGetSymbolAddress((void**)&of,  g_off);
    cudaGetSymbolAddress((void**)&wtp, g_wt);

    dim3 blk(128);

    // est = relu(conv(concat(x, rf), w_est1))
    conv3x3_k<256, 8, true,  true ><<<dim3(2, 8, B * 16), blk>>>(x,  rf,      w1, e1, 128, 16);
    // est = relu(conv(est, w_est2))
    conv3x3_k<128, 8, true,  false><<<dim3(2, 8, B * 16), blk>>>(e1, nullptr, w2, e2, 128, 16);
    // offset = conv(est, w_off)
    conv3x3_k<128, 6, false, false><<<dim3(2, 8, B * 3),  blk>>>(e2, nullptr, wo, of, 18,  3);
    // weight transpose for deform
    transpose_wdef<<<(9 * 128 * 128 + 255) / 256, 256>>>(wd, wtp);
    // out = deform_conv2d(rf, offset, w_def)
    deform_k<<<dim3(8, 16, B), blk>>>(rf, of, wtp, out);
}

// round 3
// speedup vs baseline: 1.2320x; 1.2320x over previous
#include <cuda_runtime.h>

#define HW 16384
#define WD 128

typedef unsigned long long u64;

// Scratch (allocation-free rule: __device__ globals)
__device__ float g_est1[2 * 128 * HW];   // 16 MB
__device__ float g_est2[2 * 128 * HW];   // 16 MB
__device__ float g_off [2 * 18  * HW];   // 2.25 MB
__device__ float g_wt  [9 * 128 * 128];  // w_def transposed to [k][c][o]
__device__ float g_dmy [128];

// ---- packed fp32x2 helpers -------------------------------------------------
__device__ __forceinline__ u64 pk(float lo, float hi) {
    u64 r; asm("mov.b64 %0, {%1, %2};" : "=l"(r) : "f"(lo), "f"(hi)); return r;
}
__device__ __forceinline__ void upk(u64 v, float& lo, float& hi) {
    asm("mov.b64 {%0, %1}, %2;" : "=f"(lo), "=f"(hi) : "l"(v));
}
__device__ __forceinline__ u64 fma2(u64 a, u64 b, u64 c) {
    u64 d; asm("fma.rn.f32x2 %0, %1, %2, %3;" : "=l"(d) : "l"(a), "l"(b), "l"(c));
    return d;
}

// ---------------------------------------------------------------------------
// Direct 3x3 conv, stride 1, pad 1, NCHW, H=W=128, fp32x2 math,
// DOUBLE-BUFFERED channel staging (prefetch c+1 to regs while computing c).
// Block: 128 threads, output tile 16(h) x 64(w); thread: 2 rows x 4 cols,
// OC_B output channels register-blocked.
// ---------------------------------------------------------------------------
template <int C_IN, int OC_B, bool RELU, bool CONCAT>
__global__ __launch_bounds__(128) void conv3x3_k(
    const float* __restrict__ in0, const float* __restrict__ in1,
    const float* __restrict__ wt, float* __restrict__ out,
    int C_out, int n_ocb)
{
    __shared__ __align__(16) float st[2][18 * 66];
    __shared__ u64 swd[2][OC_B * 9];

    const int tid = threadIdx.x;
    const int tx  = tid & 15;          // 16 threads across W (4 px each)
    const int ty  = tid >> 4;          // 8  threads across H (2 px each)
    const int w0  = blockIdx.x * 64;
    const int h0  = blockIdx.y * 16;
    const int b   = blockIdx.z / n_ocb;
    const int ocb = blockIdx.z % n_ocb;

    // per-thread staging descriptors (10 strided slots cover 18*66 = 1188)
    int gofs[10]; unsigned vmask = 0;
#pragma unroll
    for (int i = 0; i < 10; i++) {
        int idx = tid + i * 128;
        int r = idx / 66, q = idx - r * 66;
        int gh = h0 - 1 + r, gw = w0 - 1 + q;
        gofs[i] = gh * WD + gw;
        if (idx < 1188 && (unsigned)gh < 128u && (unsigned)gw < 128u)
            vmask |= 1u << i;
    }
    // weight staging descriptor (one weight element per thread, tid < OC_B*9)
    bool wval = false; int wbase = 0;
    if (tid < OC_B * 9) {
        int o = ocb * OC_B + tid / 9;
        wval = (o < C_out);
        wbase = o * C_IN * 9 + (tid % 9);
    }

    u64 acc[OC_B][2][2];
#pragma unroll
    for (int o = 0; o < OC_B; o++)
#pragma unroll
        for (int r = 0; r < 2; r++) { acc[o][r][0] = 0ull; acc[o][r][1] = 0ull; }

    // channel plane resolver
    auto planeof = [&](int c) -> const float* {
        if (CONCAT)
            return (c < 128) ? in0 + (size_t)(b * 128 + c) * HW
                             : in1 + (size_t)(b * 128 + (c - 128)) * HW;
        return in0 + (size_t)(b * C_IN + c) * HW;
    };

    // ---- prologue: stage channel 0 ----
    {
        const float* pl = planeof(0);
        float pf[10];
#pragma unroll
        for (int i = 0; i < 10; i++)
            pf[i] = (vmask >> i & 1) ? __ldg(pl + gofs[i]) : 0.f;
        float wpf = wval ? __ldg(wt + wbase) : 0.f;
#pragma unroll
        for (int i = 0; i < 10; i++) {
            int idx = tid + i * 128;
            if (idx < 1188) st[0][idx] = pf[i];
        }
        if (tid < OC_B * 9) swd[0][tid] = pk(wpf, wpf);
    }
    __syncthreads();

#pragma unroll 1
    for (int c = 0; c < C_IN; ++c) {
        const int cur = c & 1, nxt = cur ^ 1;

        // ---- prefetch channel c+1 into registers (latency hidden by compute)
        float pf[10]; float wpf = 0.f;
        const bool more = (c + 1 < C_IN);
        if (more) {
            const float* pl = planeof(c + 1);
#pragma unroll
            for (int i = 0; i < 10; i++)
                pf[i] = (vmask >> i & 1) ? __ldg(pl + gofs[i]) : 0.f;
            if (wval) wpf = __ldg(wt + wbase + (c + 1) * 9);
        }

        // ---- compute channel c ----
        const float* sb = st[cur] + (ty * 2) * 66 + tx * 4;
        u64 P[4][5];
#pragma unroll
        for (int r = 0; r < 4; r++) {
            const float* rp = sb + r * 66;
            float2 A  = *(const float2*)rp;
            float2 Bv = *(const float2*)(rp + 2);
            float2 D  = *(const float2*)(rp + 4);
            P[r][0] = pk(A.x, A.y);
            P[r][1] = pk(A.y, Bv.x);
            P[r][2] = pk(Bv.x, Bv.y);
            P[r][3] = pk(Bv.y, D.x);
            P[r][4] = pk(D.x, D.y);
        }
#pragma unroll
        for (int o = 0; o < OC_B; o++) {
#pragma unroll
            for (int ky = 0; ky < 3; ky++)
#pragma unroll
                for (int kx = 0; kx < 3; kx++) {
                    u64 wv = swd[cur][o * 9 + ky * 3 + kx];
                    acc[o][0][0] = fma2(P[ky][kx],         wv, acc[o][0][0]);
                    acc[o][0][1] = fma2(P[ky][kx + 2],     wv, acc[o][0][1]);
                    acc[o][1][0] = fma2(P[ky + 1][kx],     wv, acc[o][1][0]);
                    acc[o][1][1] = fma2(P[ky + 1][kx + 2], wv, acc[o][1][1]);
                }
        }

        __syncthreads();           // all reads of st[nxt] (iter c-1) long done;
                                   // all reads of st[cur] this iter done
        if (more) {
#pragma unroll
            for (int i = 0; i < 10; i++) {
                int idx = tid + i * 128;
                if (idx < 1188) st[nxt][idx] = pf[i];
            }
            if (tid < OC_B * 9) swd[nxt][tid] = pk(wpf, wpf);
        }
        __syncthreads();           // publish st[nxt] for next iteration
    }

    const int ph = h0 + ty * 2, pw = w0 + tx * 4;
#pragma unroll
    for (int o = 0; o < OC_B; o++) {
        int oc = ocb * OC_B + o;
        if (oc >= C_out) break;
        float* op = out + (size_t)(b * C_out + oc) * HW + ph * WD + pw;
#pragma unroll
        for (int r = 0; r < 2; r++) {
            float4 v;
            upk(acc[o][r][0], v.x, v.y);
            upk(acc[o][r][1], v.z, v.w);
            if (RELU) {
                v.x = fmaxf(v.x, 0.f); v.y = fmaxf(v.y, 0.f);
                v.z = fmaxf(v.z, 0.f); v.w = fmaxf(v.w, 0.f);
            }
            *(float4*)(op + r * WD) = v;
        }
    }
}

// ---------------------------------------------------------------------------
__global__ void transpose_wdef(const float* __restrict__ w, float* __restrict__ wtp)
{
    int idx = blockIdx.x * 256 + threadIdx.x;
    if (idx >= 9 * 128 * 128) return;
    int o = idx & 127;
    int c = (idx >> 7) & 127;
    int k = idx >> 14;
    wtp[idx] = w[((size_t)o * 128 + c) * 9 + k];
}

__global__ void dummy_k(float* p) { p[threadIdx.x] = 0.f; }

// ---------------------------------------------------------------------------
// Fused deformable conv, fp32x2, 64 output channels per block (low register
// pressure: 32 u64 accumulators). Block = 128 pixels (8h x 16w). Per tap k:
// stage 128c x 64o weights (32 KB); c-loop: 4 gathers + 32 fma2 via
// broadcast ulonglong2 SMEM reads.
// ---------------------------------------------------------------------------
__global__ __launch_bounds__(128) void deform_k(
    const float* __restrict__ ref, const float* __restrict__ off,
    const float* __restrict__ wtp, float* __restrict__ out)
{
    __shared__ __align__(16) float swt[128 * 64];  // 32 KB: [c][64 o]

    const int tid = threadIdx.x;
    const int w = blockIdx.x * 16 + (tid & 15);
    const int h = blockIdx.y * 8  + (tid >> 4);
    const int b  = blockIdx.z >> 1;
    const int ob = blockIdx.z & 1;

    u64 a2[32];
#pragma unroll
    for (int j = 0; j < 32; j++) a2[j] = 0ull;

    const float* offp = off + (size_t)b * 18 * HW + h * WD + w;
    const float* pb   = ref + (size_t)b * 128 * HW;

#pragma unroll 1
    for (int k = 0; k < 9; ++k) {
        // bilinear sampling parameters (per-corner validity, zero outside)
        float dy = __ldg(offp + (2 * k)     * HW);
        float dx = __ldg(offp + (2 * k + 1) * HW);
        float py = (float)(h + (k / 3) - 1) + dy;
        float px = (float)(w + (k % 3) - 1) + dx;
        float y0f = floorf(py), x0f = floorf(px);
        float wy = py - y0f, wx = px - x0f;
        int y0 = (int)y0f, x0 = (int)x0f;
        int y1 = y0 + 1,   x1 = x0 + 1;
        bool vy0 = (unsigned)y0 < 128u, vy1 = (unsigned)y1 < 128u;
        bool vx0 = (unsigned)x0 < 128u, vx1 = (unsigned)x1 < 128u;
        int y0c = min(max(y0, 0), 127), y1c = min(max(y1, 0), 127);
        int x0c = min(max(x0, 0), 127), x1c = min(max(x1, 0), 127);
        float w00 = (1.f - wy) * (1.f - wx) * ((vy0 && vx0) ? 1.f : 0.f);
        float w01 = (1.f - wy) * wx         * ((vy0 && vx1) ? 1.f : 0.f);
        float w10 = wy * (1.f - wx)         * ((vy1 && vx0) ? 1.f : 0.f);
        float w11 = wy * wx                 * ((vy1 && vx1) ? 1.f : 0.f);
        int o00 = y0c * WD + x0c, o01 = y0c * WD + x1c;
        int o10 = y1c * WD + x0c, o11 = y1c * WD + x1c;

        // stage weights for this tap: swt[c*64 + j] = wt[k][c][ob*64 + j]
        __syncthreads();
        const float* src = wtp + (size_t)k * 16384 + ob * 64;
        for (int i = tid * 4; i < 8192; i += 512) {
            int c = i >> 6, j = i & 63;
            *(float4*)(swt + i) = *(const float4*)(src + c * 128 + j);
        }
        __syncthreads();

        // channel loop: gather + accumulate 64 output channels (32 fma2)
#pragma unroll 4
        for (int c = 0; c < 128; ++c) {
            const float* pl = pb + (size_t)c * HW;
            float s = w00 * __ldg(pl + o00) + w01 * __ldg(pl + o01)
                    + w10 * __ldg(pl + o10) + w11 * __ldg(pl + o11);
            u64 ss = pk(s, s);
            const ulonglong2* wr = (const ulonglong2*)(swt + c * 64);
#pragma unroll
            for (int j = 0; j < 16; j++) {
                ulonglong2 wv = wr[j];
                a2[2 * j]     = fma2(wv.x, ss, a2[2 * j]);
                a2[2 * j + 1] = fma2(wv.y, ss, a2[2 * j + 1]);
            }
        }
    }

    float* op = out + ((size_t)b * 128 + ob * 64) * HW + h * WD + w;
#pragma unroll
    for (int j = 0; j < 32; j++) {
        float v0, v1;
        upk(a2[j], v0, v1);
        op[(size_t)(2 * j)     * HW] = v0;
        op[(size_t)(2 * j + 1) * HW] = v1;
    }
}

// ---------------------------------------------------------------------------
extern "C" void kernel_launch(void* const* d_in, const int* in_sizes, int n_in,
                              void* d_out, int out_size)
{
    const float* x  = (const float*)d_in[0];  // input_features
    const float* rf = (const float*)d_in[1];  // reference_features
    const float* w1 = (const float*)d_in[2];  // w_est1 [128,256,3,3]
    const float* w2 = (const float*)d_in[3];  // w_est2 [128,128,3,3]
    const float* wo = (const float*)d_in[4];  // w_off  [18,128,3,3]
    const float* wd = (const float*)d_in[5];  // w_def  [128,128,3,3]
    float* out = (float*)d_out;

    const int B = in_sizes[0] / (128 * HW);   // 2

    float *e1, *e2, *of, *wtp, *dmy;
    cudaGetSymbolAddress((void**)&e1,  g_est1);
    cudaGetSymbolAddress((void**)&e2,  g_est2);
    cudaGetSymbolAddress((void**)&of,  g_off);
    cudaGetSymbolAddress((void**)&wtp, g_wt);
    cudaGetSymbolAddress((void**)&dmy, g_dmy);

    dim3 blk(128);

    // position 0-2: transpose + 2 dummies (puts conv1 at the profiled slot)
    transpose_wdef<<<(9 * 128 * 128 + 255) / 256, 256>>>(wd, wtp);
    dummy_k<<<1, 128>>>(dmy);
    dummy_k<<<1, 128>>>(dmy);
    // est = relu(conv(concat(x, rf), w_est1))
    conv3x3_k<256, 8, true,  true ><<<dim3(2, 8, B * 16), blk>>>(x,  rf,      w1, e1, 128, 16);
    // est = relu(conv(est, w_est2))
    conv3x3_k<128, 8, true,  false><<<dim3(2, 8, B * 16), blk>>>(e1, nullptr, w2, e2, 128, 16);
    // offset = conv(est, w_off)
    conv3x3_k<128, 6, false, false><<<dim3(2, 8, B * 3),  blk>>>(e2, nullptr, wo, of, 18,  3);
    // out = deform_conv2d(rf, offset, w_def)
    deform_k<<<dim3(8, 16, B * 2), blk>>>(rf, of, wtp, out);
}

// round 4
// speedup vs baseline: 1.6506x; 1.3398x over previous
#include <cuda_runtime.h>

#define HW 16384
#define WD 128

typedef unsigned long long u64;

// Scratch (allocation-free rule: __device__ globals)
__device__ float g_est1[2 * 128 * HW];   // 16 MB
__device__ float g_est2[2 * 128 * HW];   // 16 MB
__device__ float g_off [2 * 18  * HW];   // 2.25 MB
__device__ float g_wt  [9 * 128 * 128];  // w_def transposed to [k][c][o]
__device__ float g_dmy [128];

// ---- packed fp32x2 helpers -------------------------------------------------
__device__ __forceinline__ u64 pk(float lo, float hi) {
    u64 r; asm("mov.b64 %0, {%1, %2};" : "=l"(r) : "f"(lo), "f"(hi)); return r;
}
__device__ __forceinline__ void upk(u64 v, float& lo, float& hi) {
    asm("mov.b64 {%0, %1}, %2;" : "=f"(lo), "=f"(hi) : "l"(v));
}
__device__ __forceinline__ u64 fma2(u64 a, u64 b, u64 c) {
    u64 d; asm("fma.rn.f32x2 %0, %1, %2, %3;" : "=l"(d) : "l"(a), "l"(b), "l"(c));
    return d;
}

// ---- cp.async helpers -------------------------------------------------------
__device__ __forceinline__ unsigned sm32(const void* p) {
    return (unsigned)__cvta_generic_to_shared(p);
}
__device__ __forceinline__ void cpa4(unsigned s, const float* g, bool v) {
    asm volatile("cp.async.ca.shared.global [%0], [%1], 4, %2;"
                 :: "r"(s), "l"(g), "r"(v ? 4u : 0u));
}
__device__ __forceinline__ void cpa_commit() {
    asm volatile("cp.async.commit_group;");
}
template <int N>
__device__ __forceinline__ void cpa_wait() {
    asm volatile("cp.async.wait_group %0;" :: "n"(N));
}

// ---------------------------------------------------------------------------
// Direct 3x3 conv, stride 1, pad 1, NCHW, H=W=128, fp32x2 math.
// cp.async staging into a 4-stage ring, prefetch distance 2, ONE barrier per
// channel. Block: 128 threads; tile 16(h) x 64(w); thread: 2 rows x 4 cols;
// OC_B output channels register-blocked.
// ---------------------------------------------------------------------------
template <int C_IN, int OC_B, bool RELU, bool CONCAT>
__global__ __launch_bounds__(128) void conv3x3_k(
    const float* __restrict__ in0, const float* __restrict__ in1,
    const float* __restrict__ wt, float* __restrict__ out,
    int C_out, int n_ocb)
{
    __shared__ __align__(16) float st[4][18 * 66];   // 4 x 4752 B
    __shared__ u64 swd[4][OC_B * 9];

    const int tid = threadIdx.x;
    const int tx  = tid & 15;          // 16 threads across W (4 px each)
    const int ty  = tid >> 4;          // 8  threads across H (2 px each)
    const int w0  = blockIdx.x * 64;
    const int h0  = blockIdx.y * 16;
    const int b   = blockIdx.z / n_ocb;
    const int ocb = blockIdx.z % n_ocb;

    // staging descriptors: 10 strided slots cover 18*66 = 1188 elements
    int gofs[10]; unsigned vmask = 0;
#pragma unroll
    for (int i = 0; i < 10; i++) {
        int idx = tid + i * 128;
        int r = idx / 66, q = idx - r * 66;
        int gh = h0 - 1 + r, gw = w0 - 1 + q;
        gofs[i] = gh * WD + gw;
        if ((unsigned)gh < 128u && (unsigned)gw < 128u)
            vmask |= 1u << i;
    }
    const unsigned sbase = sm32(&st[0][0]) + tid * 4;

    bool wv = false; int wbase = 0;
    if (tid < OC_B * 9) {
        int o = ocb * OC_B + tid / 9;
        wv = (o < C_out);
        wbase = o * C_IN * 9 + (tid % 9);
    }

    auto planeof = [&](int c) -> const float* {
        if (CONCAT)
            return (c < 128) ? in0 + (size_t)(b * 128 + c) * HW
                             : in1 + (size_t)(b * 128 + (c - 128)) * HW;
        return in0 + (size_t)(b * C_IN + c) * HW;
    };

    auto issue = [&](int c) {
        const float* pl = planeof(c);
        unsigned sd = sbase + (c & 3) * 4752;
#pragma unroll
        for (int i = 0; i < 9; i++) {
            bool p = (vmask >> i) & 1;
            cpa4(sd + i * 512, p ? pl + gofs[i] : pl, p);
        }
        if (tid < 36) {   // slot 9: idx = tid + 1152 < 1188
            bool p = (vmask >> 9) & 1;
            cpa4(sd + 9 * 512, p ? pl + gofs[9] : pl, p);
        }
        cpa_commit();
    };

    u64 acc[OC_B][2][2];
#pragma unroll
    for (int o = 0; o < OC_B; o++)
#pragma unroll
        for (int r = 0; r < 2; r++) { acc[o][r][0] = 0ull; acc[o][r][1] = 0ull; }

    // ---- prologue: stages 0,1 in flight; weight reg holds channel 2 ----
    issue(0); issue(1);
    float wreg = 0.f;
    if (tid < OC_B * 9) {
        float t0 = wv ? __ldg(wt + wbase)      : 0.f;
        float t1 = wv ? __ldg(wt + wbase + 9)  : 0.f;
        wreg     = wv ? __ldg(wt + wbase + 18) : 0.f;
        swd[0][tid] = pk(t0, t0);
        swd[1][tid] = pk(t1, t1);
    }

#pragma unroll 1
    for (int c = 0; c < C_IN; ++c) {
        if (c + 2 < C_IN) {
            issue(c + 2);
            if (tid < OC_B * 9) {
                swd[(c + 2) & 3][tid] = pk(wreg, wreg);
                wreg = (wv && c + 3 < C_IN) ? __ldg(wt + wbase + (c + 3) * 9) : 0.f;
            }
            cpa_wait<2>();
        } else {
            cpa_wait<0>();
        }
        __syncthreads();

        // ---- compute channel c from st[c&3], swd[c&3] ----
        const float* sb = st[c & 3] + (ty * 2) * 66 + tx * 4;
        u64 P[4][5];
#pragma unroll
        for (int r = 0; r < 4; r++) {
            const float* rp = sb + r * 66;
            float2 A  = *(const float2*)rp;
            float2 Bv = *(const float2*)(rp + 2);
            float2 D  = *(const float2*)(rp + 4);
            P[r][0] = pk(A.x, A.y);
            P[r][1] = pk(A.y, Bv.x);
            P[r][2] = pk(Bv.x, Bv.y);
            P[r][3] = pk(Bv.y, D.x);
            P[r][4] = pk(D.x, D.y);
        }
        const u64* wrow = swd[c & 3];
#pragma unroll
        for (int o = 0; o < OC_B; o++) {
#pragma unroll
            for (int ky = 0; ky < 3; ky++)
#pragma unroll
                for (int kx = 0; kx < 3; kx++) {
                    u64 wvv = wrow[o * 9 + ky * 3 + kx];
                    acc[o][0][0] = fma2(P[ky][kx],         wvv, acc[o][0][0]);
                    acc[o][0][1] = fma2(P[ky][kx + 2],     wvv, acc[o][0][1]);
                    acc[o][1][0] = fma2(P[ky + 1][kx],     wvv, acc[o][1][0]);
                    acc[o][1][1] = fma2(P[ky + 1][kx + 2], wvv, acc[o][1][1]);
                }
        }
        __syncthreads();   // all reads of st[c&3]/swd[c&3] done before reuse
    }

    const int ph = h0 + ty * 2, pw = w0 + tx * 4;
#pragma unroll
    for (int o = 0; o < OC_B; o++) {
        int oc = ocb * OC_B + o;
        if (oc >= C_out) break;
        float* op = out + (size_t)(b * C_out + oc) * HW + ph * WD + pw;
#pragma unroll
        for (int r = 0; r < 2; r++) {
            float4 v;
            upk(acc[o][r][0], v.x, v.y);
            upk(acc[o][r][1], v.z, v.w);
            if (RELU) {
                v.x = fmaxf(v.x, 0.f); v.y = fmaxf(v.y, 0.f);
                v.z = fmaxf(v.z, 0.f); v.w = fmaxf(v.w, 0.f);
            }
            *(float4*)(op + r * WD) = v;
        }
    }
}

// ---------------------------------------------------------------------------
__global__ void transpose_wdef(const float* __restrict__ w, float* __restrict__ wtp)
{
    int idx = blockIdx.x * 256 + threadIdx.x;
    if (idx >= 9 * 128 * 128) return;
    int o = idx & 127;
    int c = (idx >> 7) & 127;
    int k = idx >> 14;
    wtp[idx] = w[((size_t)o * 128 + c) * 9 + k];
}

__global__ void dummy_k(float* p) { p[threadIdx.x] = 0.f; }

// ---------------------------------------------------------------------------
// Fused deformable conv v3. Block: 256 threads, 128 pixels (8h x 16w),
// ALL 128 output channels (every bilinear sample loaded exactly once).
// Flattened (tap, chunk) loop: 9 taps x 4 chunks of 32 channels.
// Pipeline: gather chunk i+1 into regs while computing chunk i from SMEM.
// Gather mapping : thread -> (pixel tid&127, 16 channels).
// Compute mapping: thread -> (pixel pair (tid&63)*2, oc quarter tid>>6):
//   per channel 1 LDS.64 (s pair) + 8 LDS.128 (weights) + 32 fma2.
// ---------------------------------------------------------------------------
__global__ __launch_bounds__(256) void deform_k(
    const float* __restrict__ ref, const float* __restrict__ off,
    const float* __restrict__ wtp, float* __restrict__ out)
{
    __shared__ __align__(16) float s_s[32 * 128];  // [c_local][px]  16 KB
    __shared__ __align__(16) float s_w[32 * 128];  // [c_local][oc]  16 KB

    const int tid  = threadIdx.x;
    const int pxg  = tid & 127;          // gather pixel
    const int ch16 = (tid >> 7) * 16;    // gather channel sub-block
    const int wg = blockIdx.x * 16 + (pxg & 15);
    const int hg = blockIdx.y * 8  + (pxg >> 4);
    const int b  = blockIdx.z;

    const int pxc = (tid & 63) * 2;      // compute pixel pair base
    const int q   = tid >> 6;            // oc quarter (0..3)
    const int wc = blockIdx.x * 16 + (pxc & 15);
    const int hc = blockIdx.y * 8  + (pxc >> 4);

    u64 a2[2][16];
#pragma unroll
    for (int p = 0; p < 2; p++)
#pragma unroll
        for (int j = 0; j < 16; j++) a2[p][j] = 0ull;

    const float* offp = off + (size_t)b * 18 * HW + hg * WD + wg;
    const float* pb   = ref + (size_t)b * 128 * HW;

    float  sv[16];
    float4 wv4[4];

    auto gather = [&](int it) {
        const int k = it >> 2, chunk = it & 3;
        float dy = __ldg(offp + (2 * k)     * HW);
        float dx = __ldg(offp + (2 * k + 1) * HW);
        float py = (float)(hg + (k / 3) - 1) + dy;
        float px = (float)(wg + (k % 3) - 1) + dx;
        float y0f = floorf(py), x0f = floorf(px);
        float wy = py - y0f, wx = px - x0f;
        int y0 = (int)y0f, x0 = (int)x0f;
        int y1 = y0 + 1,   x1 = x0 + 1;
        bool vy0 = (unsigned)y0 < 128u, vy1 = (unsigned)y1 < 128u;
        bool vx0 = (unsigned)x0 < 128u, vx1 = (unsigned)x1 < 128u;
        int y0c = min(max(y0, 0), 127), y1c = min(max(y1, 0), 127);
        int x0c = min(max(x0, 0), 127), x1c = min(max(x1, 0), 127);
        float w00 = (1.f - wy) * (1.f - wx) * ((vy0 && vx0) ? 1.f : 0.f);
        float w01 = (1.f - wy) * wx         * ((vy0 && vx1) ? 1.f : 0.f);
        float w10 = wy * (1.f - wx)         * ((vy1 && vx0) ? 1.f : 0.f);
        float w11 = wy * wx                 * ((vy1 && vx1) ? 1.f : 0.f);
        int o00 = y0c * WD + x0c, o01 = y0c * WD + x1c;
        int o10 = y1c * WD + x0c, o11 = y1c * WD + x1c;

        const float* plb = pb + (size_t)(chunk * 32 + ch16) * HW;
#pragma unroll
        for (int i = 0; i < 16; i++) {
            const float* pl = plb + (size_t)i * HW;
            sv[i] = w00 * __ldg(pl + o00) + w01 * __ldg(pl + o01)
                  + w10 * __ldg(pl + o10) + w11 * __ldg(pl + o11);
        }
        const float4* wsrc = (const float4*)(wtp + (size_t)k * 16384 + chunk * 32 * 128);
#pragma unroll
        for (int j = 0; j < 4; j++) wv4[j] = __ldg(wsrc + tid + j * 256);
    };

    gather(0);

#pragma unroll 1
    for (int it = 0; it < 36; ++it) {
        __syncthreads();   // previous compute done reading s_s / s_w
#pragma unroll
        for (int i = 0; i < 16; i++) s_s[(ch16 + i) * 128 + pxg] = sv[i];
        {
            float4* wd = (float4*)s_w;
#pragma unroll
            for (int j = 0; j < 4; j++) wd[tid + j * 256] = wv4[j];
        }
        __syncthreads();

        if (it + 1 < 36) gather(it + 1);   // LDG latency hidden by compute

#pragma unroll 4
        for (int c = 0; c < 32; ++c) {
            float2 s2 = *(const float2*)(s_s + c * 128 + pxc);
            u64 ss0 = pk(s2.x, s2.x);
            u64 ss1 = pk(s2.y, s2.y);
            const ulonglong2* wr = (const ulonglong2*)(s_w + c * 128 + q * 32);
#pragma unroll
            for (int j = 0; j < 8; j++) {
                ulonglong2 w2 = wr[j];
                a2[0][2 * j]     = fma2(w2.x, ss0, a2[0][2 * j]);
                a2[0][2 * j + 1] = fma2(w2.y, ss0, a2[0][2 * j + 1]);
                a2[1][2 * j]     = fma2(w2.x, ss1, a2[1][2 * j]);
                a2[1][2 * j + 1] = fma2(w2.y, ss1, a2[1][2 * j + 1]);
            }
        }
    }

    // stores: oc = q*32 + 2j (+1); pixel pair (wc, wc+1) -> float2, coalesced
    float* ob = out + (size_t)(b * 128 + q * 32) * HW + hc * WD + wc;
#pragma unroll
    for (int j = 0; j < 16; j++) {
        float v0, v1, u0, u1;
        upk(a2[0][j], v0, v1);
        upk(a2[1][j], u0, u1);
        float2 e; e.x = v0; e.y = u0;
        float2 f; f.x = v1; f.y = u1;
        *(float2*)(ob + (size_t)(2 * j)     * HW) = e;
        *(float2*)(ob + (size_t)(2 * j + 1) * HW) = f;
    }
}

// ---------------------------------------------------------------------------
extern "C" void kernel_launch(void* const* d_in, const int* in_sizes, int n_in,
                              void* d_out, int out_size)
{
    const float* x  = (const float*)d_in[0];  // input_features
    const float* rf = (const float*)d_in[1];  // reference_features
    const float* w1 = (const float*)d_in[2];  // w_est1 [128,256,3,3]
    const float* w2 = (const float*)d_in[3];  // w_est2 [128,128,3,3]
    const float* wo = (const float*)d_in[4];  // w_off  [18,128,3,3]
    const float* wd = (const float*)d_in[5];  // w_def  [128,128,3,3]
    float* out = (float*)d_out;

    const int B = in_sizes[0] / (128 * HW);   // 2

    float *e1, *e2, *of, *wtp, *dmy;
    cudaGetSymbolAddress((void**)&e1,  g_est1);
    cudaGetSymbolAddress((void**)&e2,  g_est2);
    cudaGetSymbolAddress((void**)&of,  g_off);
    cudaGetSymbolAddress((void**)&wtp, g_wt);
    cudaGetSymbolAddress((void**)&dmy, g_dmy);

    dim3 blk(128);

    // launches 1-3 (dummies + transpose) put conv1 in the profiled slot
    dummy_k<<<1, 128>>>(dmy);
    dummy_k<<<1, 128>>>(dmy);
    transpose_wdef<<<(9 * 128 * 128 + 255) / 256, 256>>>(wd, wtp);
    // est = relu(conv(concat(x, rf), w_est1))
    conv3x3_k<256, 4, true,  true ><<<dim3(2, 8, B * 32), blk>>>(x,  rf,      w1, e1, 128, 32);
    // est = relu(conv(est, w_est2))
    conv3x3_k<128, 4, true,  false><<<dim3(2, 8, B * 32), blk>>>(e1, nullptr, w2, e2, 128, 32);
    // offset = conv(est, w_off)
    conv3x3_k<128, 4, false, false><<<dim3(2, 8, B * 5),  blk>>>(e2, nullptr, wo, of, 18,  5);
    // out = deform_conv2d(rf, offset, w_def)
    deform_k<<<dim3(8, 16, B), 256>>>(rf, of, wtp, out);
}

// round 5
// speedup vs baseline: 1.8179x; 1.1013x over previous
#include <cuda_runtime.h>

#define HW 16384
#define WD 128

typedef unsigned long long u64;

// Scratch (allocation-free rule: __device__ globals)
__device__ float g_est1[2 * 128 * HW];   // 16 MB
__device__ float g_est2[2 * 128 * HW];   // 16 MB
__device__ float g_off [2 * 18  * HW];   // 2.25 MB
__device__ float g_wt  [9 * 128 * 128];  // w_def transposed to [k][c][o]
__device__ float g_dmy [128];

// ---- packed fp32x2 helpers -------------------------------------------------
__device__ __forceinline__ u64 pk(float lo, float hi) {
    u64 r; asm("mov.b64 %0, {%1, %2};" : "=l"(r) : "f"(lo), "f"(hi)); return r;
}
__device__ __forceinline__ void upk(u64 v, float& lo, float& hi) {
    asm("mov.b64 {%0, %1}, %2;" : "=f"(lo), "=f"(hi) : "l"(v));
}
__device__ __forceinline__ u64 fma2(u64 a, u64 b, u64 c) {
    u64 d; asm("fma.rn.f32x2 %0, %1, %2, %3;" : "=l"(d) : "l"(a), "l"(b), "l"(c));
    return d;
}

// ---- cp.async helpers --------------------------------------------------------
__device__ __forceinline__ unsigned sm32(const void* p) {
    return (unsigned)__cvta_generic_to_shared(p);
}
__device__ __forceinline__ void cpa16(unsigned s, const float* g, bool v) {
    asm volatile("cp.async.cg.shared.global [%0], [%1], 16, %2;"
                 :: "r"(s), "l"(g), "r"(v ? 16u : 0u));
}
__device__ __forceinline__ void cpa_commit() {
    asm volatile("cp.async.commit_group;");
}
template <int N>
__device__ __forceinline__ void cpa_wait() {
    asm volatile("cp.async.wait_group %0;" :: "n"(N));
}

// ---------------------------------------------------------------------------
// Direct 3x3 conv, stride 1, pad 1, NCHW, H=W=128, fp32x2 math.
// 16-BYTE cp.async staging: each channel's halo tile stored as 18 rows x 72
// floats (aligned cover of [w0-4, w0+68)); 324 float4 copies per channel.
// 2 channels per pipeline stage, 4-stage ring, 3 stages in flight, ONE
// __syncthreads per stage. Block: 128 threads; output tile 16(h) x 64(w);
// thread: 2 rows x 4 cols; OC_B output channels register-blocked.
// ---------------------------------------------------------------------------
template <int C_IN, int OC_B, bool RELU, bool CONCAT>
__global__ __launch_bounds__(128, 5) void conv3x3_k(
    const float* __restrict__ in0, const float* __restrict__ in1,
    const float* __restrict__ wt, float* __restrict__ out,
    int C_out, int n_ocb)
{
    // stage buffer: [4 stages][2 ch][18 rows * 72 floats]
    __shared__ __align__(16) float st[4][2 * 1296];
    __shared__ u64 swd[4][2 * OC_B * 9];

    const int tid = threadIdx.x;
    const int tx  = tid & 15;          // 16 threads across W (4 px each)
    const int ty  = tid >> 4;          // 8  threads across H (2 px each)
    const int w0  = blockIdx.x * 64;
    const int h0  = blockIdx.y * 16;
    const int b   = blockIdx.z / n_ocb;
    const int ocb = blockIdx.z % n_ocb;

    const int S = C_IN / 2;            // pipeline stages

    // staging descriptors: 324 float4 per channel; 3 strided slots
    int goff[3]; bool val[3];
#pragma unroll
    for (int i = 0; i < 3; i++) {
        int idx = tid + i * 128;       // float4 index
        int r = idx / 18, q = idx - r * 18;
        int gh = h0 - 1 + r;
        int gws = w0 - 4 + q * 4;
        goff[i] = gh * WD + gws;
        val[i]  = (idx < 324) && ((unsigned)gh < 128u) &&
                  (gws >= 0) && (gws <= 124);
    }
    const unsigned sst = sm32(&st[0][0]);

    // weight descriptor: tid < 72 handles one (ch-in-stage, o, tap) entry
    bool wv = false; int o_w = 0, tap_w = 0, s2_w = 0;
    if (tid < 2 * OC_B * 9) {
        s2_w  = tid / (OC_B * 9);
        int t = tid - s2_w * (OC_B * 9);
        o_w   = ocb * OC_B + t / 9;
        tap_w = t % 9;
        wv    = (o_w < C_out);
    }
    auto wld = [&](int s) -> float {   // weight for stage s, this thread
        int c = s * 2 + s2_w;
        return wv ? __ldg(wt + ((size_t)o_w * C_IN + c) * 9 + tap_w) : 0.f;
    };

    auto planeof = [&](int c) -> const float* {
        if (CONCAT)
            return (c < 128) ? in0 + (size_t)(b * 128 + c) * HW
                             : in1 + (size_t)(b * 128 + (c - 128)) * HW;
        return in0 + (size_t)(b * C_IN + c) * HW;
    };

    auto issueIn = [&](int s) {        // cp.async both channels of stage s
#pragma unroll
        for (int s2 = 0; s2 < 2; s2++) {
            const float* pl = planeof(s * 2 + s2);
            unsigned dst = sst + ((s & 3) * 2592 + s2 * 1296) * 4;
            cpa16(dst + (tid      ) * 16, pl + goff[0], val[0]);
            cpa16(dst + (tid + 128) * 16, pl + goff[1], val[1]);
            if (tid < 68)
                cpa16(dst + (tid + 256) * 16, pl + goff[2], val[2]);
        }
    };

    u64 acc[OC_B][2][2];
#pragma unroll
    for (int o = 0; o < OC_B; o++)
#pragma unroll
        for (int r = 0; r < 2; r++) { acc[o][r][0] = 0ull; acc[o][r][1] = 0ull; }

    // ---- prologue: stages 0,1,2 in flight; weights: stage0 in SMEM, stage1 in reg
    issueIn(0); cpa_commit();
    issueIn(1); cpa_commit();
    issueIn(2); cpa_commit();
    float wreg = 0.f;
    if (tid < 2 * OC_B * 9) {
        float t0 = wld(0);
        swd[0][tid] = pk(t0, t0);
        wreg = wld(1);
    }

#pragma unroll 1
    for (int s = 0; s < S; ++s) {
        cpa_wait<2>();                 // stage s input complete
        __syncthreads();               // publish stage s; all readers of the
                                       // ring slot being refilled are done
        if (s + 3 < S) issueIn(s + 3);
        cpa_commit();                  // uniform group count (may be empty)
        if (tid < 2 * OC_B * 9) {
            if (s + 1 < S) swd[(s + 1) & 3][tid] = pk(wreg, wreg);
            wreg = (s + 2 < S) ? wld(s + 2) : 0.f;
        }

        // ---- compute the 2 channels of stage s ----
        const float* sbuf = st[s & 3];
        const u64*   wbuf = swd[s & 3];
#pragma unroll
        for (int s2 = 0; s2 < 2; s2++) {
            const float* rowb = sbuf + s2 * 1296 + (ty * 2) * 72 + tx * 4;
            u64 P[4][5];
#pragma unroll
            for (int r = 0; r < 4; r++) {
                const float* rp = rowb + r * 72;
                float  l  = rp[3];
                float4 X  = *(const float4*)(rp + 4);
                float  rr = rp[8];
                P[r][0] = pk(l,   X.x);
                P[r][1] = pk(X.x, X.y);
                P[r][2] = pk(X.y, X.z);
                P[r][3] = pk(X.z, X.w);
                P[r][4] = pk(X.w, rr);
            }
            const u64* wrow = wbuf + s2 * OC_B * 9;
#pragma unroll
            for (int o = 0; o < OC_B; o++) {
#pragma unroll
                for (int ky = 0; ky < 3; ky++)
#pragma unroll
                    for (int kx = 0; kx < 3; kx++) {
                        u64 wvv = wrow[o * 9 + ky * 3 + kx];
                        acc[o][0][0] = fma2(P[ky][kx],         wvv, acc[o][0][0]);
                        acc[o][0][1] = fma2(P[ky][kx + 2],     wvv, acc[o][0][1]);
                        acc[o][1][0] = fma2(P[ky + 1][kx],     wvv, acc[o][1][0]);
                        acc[o][1][1] = fma2(P[ky + 1][kx + 2], wvv, acc[o][1][1]);
                    }
            }
        }
    }

    const int ph = h0 + ty * 2, pw = w0 + tx * 4;
#pragma unroll
    for (int o = 0; o < OC_B; o++) {
        int oc = ocb * OC_B + o;
        if (oc >= C_out) break;
        float* op = out + (size_t)(b * C_out + oc) * HW + ph * WD + pw;
#pragma unroll
        for (int r = 0; r < 2; r++) {
            float4 v;
            upk(acc[o][r][0], v.x, v.y);
            upk(acc[o][r][1], v.z, v.w);
            if (RELU) {
                v.x = fmaxf(v.x, 0.f); v.y = fmaxf(v.y, 0.f);
                v.z = fmaxf(v.z, 0.f); v.w = fmaxf(v.w, 0.f);
            }
            *(float4*)(op + r * WD) = v;
        }
    }
}

// ---------------------------------------------------------------------------
__global__ void transpose_wdef(const float* __restrict__ w, float* __restrict__ wtp)
{
    int idx = blockIdx.x * 256 + threadIdx.x;
    if (idx >= 9 * 128 * 128) return;
    int o = idx & 127;
    int c = (idx >> 7) & 127;
    int k = idx >> 14;
    wtp[idx] = w[((size_t)o * 128 + c) * 9 + k];
}

__global__ void dummy_k(float* p) { p[threadIdx.x] = 0.f; }

// ---------------------------------------------------------------------------
// Fused deformable conv v4: 256 threads, 128 pixels, all 128 output channels.
// Double-buffered SMEM (dynamic, 64 KB) -> ONE __syncthreads per iteration.
// 36 iterations = 9 taps x 4 chunks of 32 channels. Gather chunk i+1 into
// registers while computing chunk i. Weight reads are warp-uniform (broadcast).
// ---------------------------------------------------------------------------
__global__ __launch_bounds__(256, 2) void deform_k(
    const float* __restrict__ ref, const float* __restrict__ off,
    const float* __restrict__ wtp, float* __restrict__ out)
{
    extern __shared__ __align__(16) float dsm[];
    float* s_s = dsm;           // [2][32*128] sampled values [c][px]
    float* s_w = dsm + 8192;    // [2][32*128] weights        [c][oc]

    const int tid  = threadIdx.x;
    const int pxg  = tid & 127;          // gather pixel
    const int ch16 = (tid >> 7) * 16;    // gather channel sub-block
    const int wg = blockIdx.x * 16 + (pxg & 15);
    const int hg = blockIdx.y * 8  + (pxg >> 4);
    const int b  = blockIdx.z;

    const int pxc = (tid & 63) * 2;      // compute pixel pair base
    const int q   = tid >> 6;            // oc quarter (0..3)
    const int wc = blockIdx.x * 16 + (pxc & 15);
    const int hc = blockIdx.y * 8  + (pxc >> 4);

    u64 a2[2][16];
#pragma unroll
    for (int p = 0; p < 2; p++)
#pragma unroll
        for (int j = 0; j < 16; j++) a2[p][j] = 0ull;

    const float* offp = off + (size_t)b * 18 * HW + hg * WD + wg;
    const float* pb   = ref + (size_t)b * 128 * HW;

    float  sv[16];
    float4 wv4[4];

    auto gather = [&](int it) {
        const int k = it >> 2, chunk = it & 3;
        float dy = __ldg(offp + (2 * k)     * HW);
        float dx = __ldg(offp + (2 * k + 1) * HW);
        float py = (float)(hg + (k / 3) - 1) + dy;
        float px = (float)(wg + (k % 3) - 1) + dx;
        float y0f = floorf(py), x0f = floorf(px);
        float wy = py - y0f, wx = px - x0f;
        int y0 = (int)y0f, x0 = (int)x0f;
        int y1 = y0 + 1,   x1 = x0 + 1;
        bool vy0 = (unsigned)y0 < 128u, vy1 = (unsigned)y1 < 128u;
        bool vx0 = (unsigned)x0 < 128u, vx1 = (unsigned)x1 < 128u;
        int y0c = min(max(y0, 0), 127), y1c = min(max(y1, 0), 127);
        int x0c = min(max(x0, 0), 127), x1c = min(max(x1, 0), 127);
        float w00 = (1.f - wy) * (1.f - wx) * ((vy0 && vx0) ? 1.f : 0.f);
        float w01 = (1.f - wy) * wx         * ((vy0 && vx1) ? 1.f : 0.f);
        float w10 = wy * (1.f - wx)         * ((vy1 && vx0) ? 1.f : 0.f);
        float w11 = wy * wx                 * ((vy1 && vx1) ? 1.f : 0.f);
        int o00 = y0c * WD + x0c, o01 = y0c * WD + x1c;
        int o10 = y1c * WD + x0c, o11 = y1c * WD + x1c;

        const float* plb = pb + (size_t)(chunk * 32 + ch16) * HW;
#pragma unroll
        for (int i = 0; i < 16; i++) {
            const float* pl = plb + (size_t)i * HW;
            sv[i] = w00 * __ldg(pl + o00) + w01 * __ldg(pl + o01)
                  + w10 * __ldg(pl + o10) + w11 * __ldg(pl + o11);
        }
        const float4* wsrc = (const float4*)(wtp + (size_t)k * 16384 + chunk * 32 * 128);
#pragma unroll
        for (int j = 0; j < 4; j++) wv4[j] = __ldg(wsrc + tid + j * 256);
    };

    gather(0);

#pragma unroll 1
    for (int it = 0; it < 36; ++it) {
        const int buf = it & 1;
        float* ss = s_s + buf * 4096;
        float* sw = s_w + buf * 4096;
        // publish chunk `it` (regs -> SMEM). The buffer being written was last
        // read at compute(it-2), which finished before barrier(it-1).
#pragma unroll
        for (int i = 0; i < 16; i++) ss[(ch16 + i) * 128 + pxg] = sv[i];
        {
            float4* wd4 = (float4*)sw;
#pragma unroll
            for (int j = 0; j < 4; j++) wd4[tid + j * 256] = wv4[j];
        }
        __syncthreads();

        if (it + 1 < 36) gather(it + 1);   // LDG latency hidden by compute

#pragma unroll 4
        for (int c = 0; c < 32; ++c) {
            float2 s2v = *(const float2*)(ss + c * 128 + pxc);
            u64 ss0 = pk(s2v.x, s2v.x);
            u64 ss1 = pk(s2v.y, s2v.y);
            const ulonglong2* wr = (const ulonglong2*)(sw + c * 128 + q * 32);
#pragma unroll
            for (int j = 0; j < 8; j++) {
                ulonglong2 w2 = wr[j];
                a2[0][2 * j]     = fma2(w2.x, ss0, a2[0][2 * j]);
                a2[0][2 * j + 1] = fma2(w2.y, ss0, a2[0][2 * j + 1]);
                a2[1][2 * j]     = fma2(w2.x, ss1, a2[1][2 * j]);
                a2[1][2 * j + 1] = fma2(w2.y, ss1, a2[1][2 * j + 1]);
            }
        }
    }

    float* ob = out + (size_t)(b * 128 + q * 32) * HW + hc * WD + wc;
#pragma unroll
    for (int j = 0; j < 16; j++) {
        float v0, v1, u0, u1;
        upk(a2[0][j], v0, v1);
        upk(a2[1][j], u0, u1);
        float2 e; e.x = v0; e.y = u0;
        float2 f; f.x = v1; f.y = u1;
        *(float2*)(ob + (size_t)(2 * j)     * HW) = e;
        *(float2*)(ob + (size_t)(2 * j + 1) * HW) = f;
    }
}

// ---------------------------------------------------------------------------
extern "C" void kernel_launch(void* const* d_in, const int* in_sizes, int n_in,
                              void* d_out, int out_size)
{
    const float* x  = (const float*)d_in[0];  // input_features
    const float* rf = (const float*)d_in[1];  // reference_features
    const float* w1 = (const float*)d_in[2];  // w_est1 [128,256,3,3]
    const float* w2 = (const float*)d_in[3];  // w_est2 [128,128,3,3]
    const float* wo = (const float*)d_in[4];  // w_off  [18,128,3,3]
    const float* wd = (const float*)d_in[5];  // w_def  [128,128,3,3]
    float* out = (float*)d_out;

    const int B = in_sizes[0] / (128 * HW);   // 2

    float *e1, *e2, *of, *wtp, *dmy;
    cudaGetSymbolAddress((void**)&e1,  g_est1);
    cudaGetSymbolAddress((void**)&e2,  g_est2);
    cudaGetSymbolAddress((void**)&of,  g_off);
    cudaGetSymbolAddress((void**)&wtp, g_wt);
    cudaGetSymbolAddress((void**)&dmy, g_dmy);

    cudaFuncSetAttribute(deform_k,
        cudaFuncAttributeMaxDynamicSharedMemorySize, 65536);

    dim3 blk(128);

    // launches 1-3 (dummies + transpose) keep conv1 in the profiled slot
    dummy_k<<<1, 128>>>(dmy);
    dummy_k<<<1, 128>>>(dmy);
    transpose_wdef<<<(9 * 128 * 128 + 255) / 256, 256>>>(wd, wtp);
    // est = relu(conv(concat(x, rf), w_est1))
    conv3x3_k<256, 4, true,  true ><<<dim3(2, 8, B * 32), blk>>>(x,  rf,      w1, e1, 128, 32);
    // est = relu(conv(est, w_est2))
    conv3x3_k<128, 4, true,  false><<<dim3(2, 8, B * 32), blk>>>(e1, nullptr, w2, e2, 128, 32);
    // offset = conv(est, w_off)
    conv3x3_k<128, 4, false, false><<<dim3(2, 8, B * 5),  blk>>>(e2, nullptr, wo, of, 18,  5);
    // out = deform_conv2d(rf, offset, w_def)
    deform_k<<<dim3(8, 16, B), 256, 65536>>>(rf, of, wtp, out);
}